// round 2
// baseline (speedup 1.0000x reference)
#include <cuda_runtime.h>
#include <cuda_bf16.h>
#include <math.h>

// ============================================================================
// ShawAttentionMQA — fp32 SIMT, FMA-bound tiling (round 2 design)
//   scores fold: c2c + c2p = q . (k + rel)
// ============================================================================

#define S_LEN 1024
#define NH 16
#define DH 64
#define BATCH 4
#define DM 1024
#define ROWS (BATCH * S_LEN)        // 4096
#define BH (BATCH * NH)             // 64

__device__ float g_Q[ROWS * DM];                    // [b*S+i][h*64+d]
__device__ float g_K[ROWS * DH];
__device__ float g_V[ROWS * DH];
__device__ float g_Sc[(size_t)BH * S_LEN * S_LEN];  // 256 MB
__device__ float g_C[ROWS * DM];

// ---------------------------------------------------------------------------
// SGEMM 128x128x8, 8x8 microtile (4+4 split): C[M,N] = A[M,K] @ B[N,K]^T (+bias)
// Requires M%128==0, N%128==0, K%8==0.
// ---------------------------------------------------------------------------
__global__ void sgemm_nt_128(const float* __restrict__ A, const float* __restrict__ B,
                             const float* __restrict__ bias, float* __restrict__ C,
                             int M, int N, int K) {
    __shared__ float As[8][132];
    __shared__ float Bs[8][132];
    const int tid = threadIdx.x;       // 256
    const int tx = tid & 15;           // n
    const int ty = tid >> 4;           // m
    const int row0 = blockIdx.y * 128;
    const int col0 = blockIdx.x * 128;
    const int lm = tid >> 1;           // 0..127
    const int lk = (tid & 1) * 4;      // 0 or 4

    float acc[8][8] = {};

    for (int k0 = 0; k0 < K; k0 += 8) {
        float4 a4 = *(const float4*)&A[(size_t)(row0 + lm) * K + k0 + lk];
        float4 b4 = *(const float4*)&B[(size_t)(col0 + lm) * K + k0 + lk];
        As[lk + 0][lm] = a4.x; As[lk + 1][lm] = a4.y;
        As[lk + 2][lm] = a4.z; As[lk + 3][lm] = a4.w;
        Bs[lk + 0][lm] = b4.x; Bs[lk + 1][lm] = b4.y;
        Bs[lk + 2][lm] = b4.z; Bs[lk + 3][lm] = b4.w;
        __syncthreads();
        #pragma unroll
        for (int kk = 0; kk < 8; kk++) {
            float ar[8], br[8];
            *(float4*)&ar[0] = *(const float4*)&As[kk][ty * 4];
            *(float4*)&ar[4] = *(const float4*)&As[kk][ty * 4 + 64];
            *(float4*)&br[0] = *(const float4*)&Bs[kk][tx * 4];
            *(float4*)&br[4] = *(const float4*)&Bs[kk][tx * 4 + 64];
            #pragma unroll
            for (int r = 0; r < 8; r++)
                #pragma unroll
                for (int c = 0; c < 8; c++)
                    acc[r][c] += ar[r] * br[c];
        }
        __syncthreads();
    }

    #pragma unroll
    for (int rh = 0; rh < 2; rh++) {
        #pragma unroll
        for (int r = 0; r < 4; r++) {
            const int row = row0 + rh * 64 + ty * 4 + r;
            #pragma unroll
            for (int ch = 0; ch < 2; ch++) {
                const int col = col0 + ch * 64 + tx * 4;
                float4 o;
                o.x = acc[rh * 4 + r][ch * 4 + 0];
                o.y = acc[rh * 4 + r][ch * 4 + 1];
                o.z = acc[rh * 4 + r][ch * 4 + 2];
                o.w = acc[rh * 4 + r][ch * 4 + 3];
                if (bias) {
                    o.x += bias[col + 0]; o.y += bias[col + 1];
                    o.z += bias[col + 2]; o.w += bias[col + 3];
                }
                *(float4*)&C[(size_t)row * N + col] = o;
            }
        }
    }
}

// ---------------------------------------------------------------------------
// SGEMM 64x64x16 (for N=64 K/V projections): C[M,N] = A[M,K] @ B[N,K]^T
// ---------------------------------------------------------------------------
__global__ void sgemm_nt_64(const float* __restrict__ A, const float* __restrict__ B,
                            float* __restrict__ C, int M, int N, int K) {
    __shared__ float As[16][64];
    __shared__ float Bs[16][64];
    const int tid = threadIdx.x;
    const int tx = tid & 15;
    const int ty = tid >> 4;
    const int row0 = blockIdx.y * 64;
    const int col0 = blockIdx.x * 64;

    float acc[4][4] = {};

    for (int k0 = 0; k0 < K; k0 += 16) {
        for (int t = tid; t < 64 * 16; t += 256) {
            int m = t >> 4, kk = t & 15;
            As[kk][m] = A[(size_t)(row0 + m) * K + k0 + kk];
            Bs[kk][m] = B[(size_t)(col0 + m) * K + k0 + kk];
        }
        __syncthreads();
        #pragma unroll
        for (int kk = 0; kk < 16; kk++) {
            float a[4], b[4];
            *(float4*)a = *(const float4*)&As[kk][ty * 4];
            *(float4*)b = *(const float4*)&Bs[kk][tx * 4];
            #pragma unroll
            for (int r = 0; r < 4; r++)
                #pragma unroll
                for (int c = 0; c < 4; c++)
                    acc[r][c] += a[r] * b[c];
        }
        __syncthreads();
    }
    #pragma unroll
    for (int r = 0; r < 4; r++) {
        const int row = row0 + ty * 4 + r;
        float4 o = {acc[r][0], acc[r][1], acc[r][2], acc[r][3]};
        *(float4*)&C[(size_t)row * N + col0 + tx * 4] = o;
    }
}

// ---------------------------------------------------------------------------
// Scores: Sc[bh][i][j] = q[bh,i,:] . (k[b,j,:] + rel[i,j,:])
// CTA = (j-tile of 128, i). 256 thr, microtile 4bh x 8j (split-j 4+4).
// d processed in chunks of 16 so KR tile fits smem. rel streamed once.
// ---------------------------------------------------------------------------
__global__ void scores_kernel(const float* __restrict__ rel,
                              const float* __restrict__ Q,
                              const float* __restrict__ K,
                              float* __restrict__ Sc) {
    const int i  = blockIdx.y;
    const int j0 = blockIdx.x * 128;
    const int tid = threadIdx.x;     // 256
    const int ty = tid >> 4;         // 0..15 -> bh base ty*4 (4 h of same b)
    const int tx = tid & 15;         // j: {tx*4..+3} U {64+tx*4..+3}
    const int bh0 = ty * 4;
    const int b   = bh0 >> 4;

    __shared__ float Qs[64][64];        // 16 KB
    __shared__ float KRs[4][16][128];   // 32 KB  [b][d-in-chunk][j]

    // Q for all 64 bh at row i
    for (int t = tid; t < 64 * 16; t += 256) {
        int bh = t >> 4, d4 = t & 15;
        int bb = bh >> 4, h = bh & 15;
        *(float4*)&Qs[bh][d4 * 4] =
            *(const float4*)&Q[((size_t)(bb * S_LEN + i)) * DM + h * DH + d4 * 4];
    }

    float acc[4][8] = {};

    for (int d0 = 0; d0 < DH; d0 += 16) {
        __syncthreads();   // Qs ready (first iter) / previous KRs reads done
        // build KR chunk: rel read once, fanned out to 4 batch planes
        for (int t = tid; t < 512; t += 256) {
            const int j  = t & 127;
            const int d4 = t >> 7;   // 0..3
            const float4 r4 = *(const float4*)
                &rel[(((size_t)i) * S_LEN + j0 + j) * DH + d0 + d4 * 4];
            #pragma unroll
            for (int bb = 0; bb < 4; bb++) {
                const float4 k4 = *(const float4*)
                    &K[((size_t)(bb * S_LEN + j0 + j)) * DH + d0 + d4 * 4];
                KRs[bb][d4 * 4 + 0][j] = r4.x + k4.x;
                KRs[bb][d4 * 4 + 1][j] = r4.y + k4.y;
                KRs[bb][d4 * 4 + 2][j] = r4.z + k4.z;
                KRs[bb][d4 * 4 + 3][j] = r4.w + k4.w;
            }
        }
        __syncthreads();

        #pragma unroll
        for (int dg = 0; dg < 4; dg++) {
            float4 qreg[4];
            qreg[0] = *(const float4*)&Qs[bh0 + 0][d0 + dg * 4];
            qreg[1] = *(const float4*)&Qs[bh0 + 1][d0 + dg * 4];
            qreg[2] = *(const float4*)&Qs[bh0 + 2][d0 + dg * 4];
            qreg[3] = *(const float4*)&Qs[bh0 + 3][d0 + dg * 4];
            const float* qp = (const float*)qreg;
            #pragma unroll
            for (int dd = 0; dd < 4; dd++) {
                float kr[8];
                *(float4*)&kr[0] = *(const float4*)&KRs[b][dg * 4 + dd][tx * 4];
                *(float4*)&kr[4] = *(const float4*)&KRs[b][dg * 4 + dd][64 + tx * 4];
                #pragma unroll
                for (int u = 0; u < 4; u++) {
                    const float qv = qp[u * 4 + dd];
                    #pragma unroll
                    for (int v = 0; v < 8; v++)
                        acc[u][v] += qv * kr[v];
                }
            }
        }
    }

    #pragma unroll
    for (int u = 0; u < 4; u++) {
        const size_t base = ((size_t)(bh0 + u) * S_LEN + i) * S_LEN + j0;
        float4 o0 = {acc[u][0], acc[u][1], acc[u][2], acc[u][3]};
        float4 o1 = {acc[u][4], acc[u][5], acc[u][6], acc[u][7]};
        *(float4*)&Sc[base + tx * 4]      = o0;
        *(float4*)&Sc[base + 64 + tx * 4] = o1;
    }
}

// ---------------------------------------------------------------------------
// Row softmax over j, logit scale 1/8 folded into exp argument.
// ---------------------------------------------------------------------------
__global__ void softmax_kernel(float* __restrict__ Sc) {
    const size_t base = (size_t)blockIdx.x * S_LEN;
    const int tid = threadIdx.x;               // 256
    const float scale = 0.125f;

    float v[4];
    float m = -1e30f;
    #pragma unroll
    for (int k = 0; k < 4; k++) {
        v[k] = Sc[base + tid + k * 256];
        m = fmaxf(m, v[k]);
    }
    #pragma unroll
    for (int o = 16; o; o >>= 1) m = fmaxf(m, __shfl_xor_sync(0xffffffffu, m, o));
    __shared__ float red[8];
    if ((tid & 31) == 0) red[tid >> 5] = m;
    __syncthreads();
    m = red[0];
    #pragma unroll
    for (int w = 1; w < 8; w++) m = fmaxf(m, red[w]);
    __syncthreads();

    float s = 0.f;
    #pragma unroll
    for (int k = 0; k < 4; k++) {
        v[k] = expf((v[k] - m) * scale);
        s += v[k];
    }
    #pragma unroll
    for (int o = 16; o; o >>= 1) s += __shfl_xor_sync(0xffffffffu, s, o);
    __shared__ float red2[8];
    if ((tid & 31) == 0) red2[tid >> 5] = s;
    __syncthreads();
    s = red2[0];
    #pragma unroll
    for (int w = 1; w < 8; w++) s += red2[w];
    const float inv = 1.0f / s;

    #pragma unroll
    for (int k = 0; k < 4; k++) Sc[base + tid + k * 256] = v[k] * inv;
}

// ---------------------------------------------------------------------------
// Context: ctx[b, i, h*64+d] = sum_j attn[bh,i,j] * V[b,j,d]
// CTA = (128-i tile, bh). Microtile 8i x 4d. attn tile transposed in smem.
// ---------------------------------------------------------------------------
__global__ void attn_v_kernel(const float* __restrict__ attn,
                              const float* __restrict__ V,
                              float* __restrict__ ctx) {
    const int bh = blockIdx.y, b = bh >> 4, h = bh & 15;
    const int i0 = blockIdx.x * 128;
    const float* A  = attn + (size_t)bh * S_LEN * S_LEN;
    const float* Vb = V    + (size_t)b * S_LEN * DH;
    const int tid = threadIdx.x;
    const int ty = tid >> 4;     // i group of 8
    const int tx = tid & 15;     // d group of 4

    __shared__ float Ast[32][132];   // [jj][ii] transposed, padded
    __shared__ float Vs[32][64];     // [jj][d]

    float acc[8][4] = {};

    for (int j0 = 0; j0 < S_LEN; j0 += 32) {
        __syncthreads();
        for (int t = tid; t < 1024; t += 256) {
            const int ii = t >> 3, j4 = t & 7;
            const float4 a = *(const float4*)&A[(size_t)(i0 + ii) * S_LEN + j0 + j4 * 4];
            Ast[j4 * 4 + 0][ii] = a.x;
            Ast[j4 * 4 + 1][ii] = a.y;
            Ast[j4 * 4 + 2][ii] = a.z;
            Ast[j4 * 4 + 3][ii] = a.w;
        }
        for (int t = tid; t < 512; t += 256) {
            const int jj = t >> 4, d4 = t & 15;
            *(float4*)&Vs[jj][d4 * 4] =
                *(const float4*)&Vb[(size_t)(j0 + jj) * DH + d4 * 4];
        }
        __syncthreads();
        #pragma unroll
        for (int jj = 0; jj < 32; jj++) {
            float av[8], vv[4];
            *(float4*)&av[0] = *(const float4*)&Ast[jj][ty * 8];
            *(float4*)&av[4] = *(const float4*)&Ast[jj][ty * 8 + 4];
            *(float4*)vv     = *(const float4*)&Vs[jj][tx * 4];
            #pragma unroll
            for (int r = 0; r < 8; r++)
                #pragma unroll
                for (int c = 0; c < 4; c++)
                    acc[r][c] += av[r] * vv[c];
        }
    }

    #pragma unroll
    for (int r = 0; r < 8; r++) {
        const size_t row = (size_t)(b * S_LEN + i0 + ty * 8 + r);
        float4 o = {acc[r][0], acc[r][1], acc[r][2], acc[r][3]};
        *(float4*)&ctx[row * DM + h * DH + tx * 4] = o;
    }
}

// ---------------------------------------------------------------------------
extern "C" void kernel_launch(void* const* d_in, const int* in_sizes, int n_in,
                              void* d_out, int out_size) {
    const float* x   = (const float*)d_in[0];   // [4,1024,1024]
    const float* rel = (const float*)d_in[1];   // [1024,1024,64]
    const float* Wq  = (const float*)d_in[2];   // [1024,1024]
    const float* Wk  = (const float*)d_in[3];   // [64,1024]
    const float* Wv  = (const float*)d_in[4];   // [64,1024]
    const float* Wo  = (const float*)d_in[5];   // [1024,1024]
    const float* bo  = (const float*)d_in[6];   // [1024]
    float* out = (float*)d_out;                 // [4,1024,1024]

    float *Q, *K, *V, *Sc, *C;
    cudaGetSymbolAddress((void**)&Q,  g_Q);
    cudaGetSymbolAddress((void**)&K,  g_K);
    cudaGetSymbolAddress((void**)&V,  g_V);
    cudaGetSymbolAddress((void**)&Sc, g_Sc);
    cudaGetSymbolAddress((void**)&C,  g_C);

    // 1) Projections
    sgemm_nt_128<<<dim3(DM / 128, ROWS / 128), 256>>>(x, Wq, nullptr, Q, ROWS, DM, DM);
    sgemm_nt_64 <<<dim3(1, ROWS / 64), 256>>>(x, Wk, K, ROWS, DH, DM);
    sgemm_nt_64 <<<dim3(1, ROWS / 64), 256>>>(x, Wv, V, ROWS, DH, DM);

    // 2) Scores: q . (k + rel), rel streamed once
    scores_kernel<<<dim3(S_LEN / 128, S_LEN), 256>>>(rel, Q, K, Sc);

    // 3) Softmax
    softmax_kernel<<<BH * S_LEN, 256>>>(Sc);

    // 4) attn @ V
    attn_v_kernel<<<dim3(S_LEN / 128, BH), 256>>>(Sc, V, C);

    // 5) Output projection + bias
    sgemm_nt_128<<<dim3(DM / 128, ROWS / 128), 256>>>(C, Wo, bo, out, ROWS, DM, DM);
}

// round 13
// speedup vs baseline: 1.9934x; 1.9934x over previous
#include <cuda_runtime.h>
#include <cuda_bf16.h>
#include <math.h>
#include <stdint.h>

// ============================================================================
// ShawAttentionMQA — round 13: mma.sync (HMMA base ISA) + cp.async pipelined
// GEMMs, bf16 hi/lo split precision (3 products), fp32 softmax.
// Fused hi/lo-split epilogues (Q and ctx never hit DRAM as fp32).
// Audited 4x; resubmitted unchanged pending first hardware run.
// ============================================================================

#define S_LEN 1024
#define NH 16
#define DH 64
#define BATCH 4
#define DM 1024
#define ROWS (BATCH * S_LEN)        // 4096
#define BH (BATCH * NH)             // 64

__device__ float g_KV[ROWS * 128];                  // cols 0-63 = K, 64-127 = V
__device__ float g_Sc[(size_t)BH * S_LEN * S_LEN];  // 256 MB

__device__ __nv_bfloat16 g_xhi[ROWS * DM], g_xlo[ROWS * DM];
__device__ __nv_bfloat16 g_chi[ROWS * DM], g_clo[ROWS * DM];
__device__ __nv_bfloat16 g_qhi[ROWS * DM], g_qlo[ROWS * DM];
__device__ __nv_bfloat16 g_wqhi[DM * DM], g_wqlo[DM * DM];
__device__ __nv_bfloat16 g_wohi[DM * DM], g_wolo[DM * DM];
__device__ __nv_bfloat16 g_wkvhi[128 * DM], g_wkvlo[128 * DM];   // [Wk;Wv]
__device__ __nv_bfloat16 g_vthi[BATCH * DH * S_LEN], g_vtlo[BATCH * DH * S_LEN];

// ===================== helpers =============================================
__device__ __forceinline__ uint32_t smem_u32(const void* p) {
    uint32_t a;
    asm("{ .reg .u64 t; cvta.to.shared.u64 t, %1; cvt.u32.u64 %0, t; }"
        : "=r"(a) : "l"(p));
    return a;
}

__device__ __forceinline__ void ldsm4(uint32_t* r, uint32_t addr) {
    asm volatile("ldmatrix.sync.aligned.m8n8.x4.shared.b16 {%0,%1,%2,%3}, [%4];"
        : "=r"(r[0]), "=r"(r[1]), "=r"(r[2]), "=r"(r[3]) : "r"(addr));
}

__device__ __forceinline__ void mma16816(float* c, const uint32_t* a, const uint32_t* b) {
    asm volatile(
        "mma.sync.aligned.m16n8k16.row.col.f32.bf16.bf16.f32 "
        "{%0,%1,%2,%3}, {%4,%5,%6,%7}, {%8,%9}, {%0,%1,%2,%3};"
        : "+f"(c[0]), "+f"(c[1]), "+f"(c[2]), "+f"(c[3])
        : "r"(a[0]), "r"(a[1]), "r"(a[2]), "r"(a[3]), "r"(b[0]), "r"(b[1]));
}

__device__ __forceinline__ void cp_async16(uint32_t saddr, const void* g) {
    asm volatile("cp.async.cg.shared.global [%0], [%1], 16;"
                 :: "r"(saddr), "l"(g) : "memory");
}
#define CP_COMMIT() asm volatile("cp.async.commit_group;" ::: "memory")
#define CP_WAIT(n)  asm volatile("cp.async.wait_group %0;" :: "n"(n) : "memory")

__device__ __forceinline__ uint32_t pack_bf16x2(float x, float y) {
    __nv_bfloat162 t = __floats2bfloat162_rn(x, y);
    return *(uint32_t*)&t;
}

// split v -> (hi, lo) exactly as split_bf16 kernel does
__device__ __forceinline__ void split2(float v, float& hf, float& lf) {
    __nv_bfloat16 hb = __float2bfloat16(v);
    hf = __bfloat162float(hb);
    lf = v - hf;
}

// A-fragment ldmatrix address (m16 x k16 tile, row-major smem [m][k])
__device__ __forceinline__ uint32_t a_addr(uint32_t base, int stride, int m0,
                                           int kbyte, int lane) {
    return base + (uint32_t)(m0 + (lane & 15)) * stride + kbyte + ((lane >> 4) << 4);
}
// B-fragment ldmatrix address: covers 2 n-tiles (n0, n0+8) x k16; smem [n][k]
__device__ __forceinline__ uint32_t b_addr(uint32_t base, int stride, int n0,
                                           int kbyte, int lane) {
    return base + (uint32_t)(n0 + ((lane >> 4) << 3) + (lane & 7)) * stride
               + kbyte + (((lane >> 3) & 1) << 4);
}

// ---------------------------------------------------------------------------
__global__ void split_bf16(const float* __restrict__ src,
                           __nv_bfloat16* __restrict__ hi,
                           __nv_bfloat16* __restrict__ lo, int n) {
    int i = blockIdx.x * 256 + threadIdx.x;
    if (i < n) {
        float x = src[i];
        __nv_bfloat16 h = __float2bfloat16(x);
        hi[i] = h;
        lo[i] = __float2bfloat16(x - __bfloat162float(h));
    }
}

// V^T split: vt[b][d][j] = split(KV[b*S+j][64+d])
__global__ void vt_split(const float* __restrict__ KV,
                         __nv_bfloat16* __restrict__ vthi,
                         __nv_bfloat16* __restrict__ vtlo) {
    const int t = blockIdx.x * 256 + threadIdx.x;   // 4096 = b*1024 + j
    const int b = t >> 10, j = t & 1023;
    const float* src = &KV[((size_t)(b * S_LEN + j)) * 128 + 64];
    #pragma unroll
    for (int d = 0; d < DH; d++) {
        float v = src[d];
        __nv_bfloat16 h = __float2bfloat16(v);
        vthi[((size_t)(b * DH + d)) * S_LEN + j] = h;
        vtlo[((size_t)(b * DH + d)) * S_LEN + j] =
            __float2bfloat16(v - __bfloat162float(h));
    }
}

// ---------------------------------------------------------------------------
// Projection GEMM: 128x128 per CTA of A[M,1024] @ B[N,1024]^T (+bias).
// Outputs: fp32 C (optional) and/or fused bf16 hi/lo split (optional).
// 8 warps, warp tile 64x32. BK=32, cp.async double buffer. 3 split products.
// ---------------------------------------------------------------------------
#define KD 1024
#define PSTR 80

__global__ void __launch_bounds__(256, 1)
mma_gemm(const __nv_bfloat16* __restrict__ Ahi, const __nv_bfloat16* __restrict__ Alo,
         const __nv_bfloat16* __restrict__ Bhi, const __nv_bfloat16* __restrict__ Blo,
         const float* __restrict__ bias, float* __restrict__ C,
         __nv_bfloat16* __restrict__ Chi, __nv_bfloat16* __restrict__ Clo, int ldc) {
    __shared__ char smem[2 * 2 * 128 * PSTR];      // [buf][A/B][128 rows][80B]
    const uint32_t smbase = smem_u32(smem);
    const int tid = threadIdx.x;
    const int wid = tid >> 5;
    const int lane = tid & 31;
    const int wm = wid >> 2;       // 0..1
    const int wn = wid & 3;        // 0..3
    const int row0 = blockIdx.y * 128;
    const int col0 = blockIdx.x * 128;

    float acc[4][4][4] = {};       // [mt][nt][4]

    auto load_async = [&](int c, int buf) {
        const int p = c >> 5;                       // 0:hi*hi 1:hi*lo 2:lo*hi
        const int k0 = (c & 31) * 32;
        const __nv_bfloat16* Ap = (p == 2) ? Alo : Ahi;
        const __nv_bfloat16* Bp = (p == 1) ? Blo : Bhi;
        const uint32_t sA = smbase + buf * 2 * 128 * PSTR;
        const uint32_t sB = sA + 128 * PSTR;
        #pragma unroll
        for (int t = tid; t < 512; t += 256) {
            const int row = t >> 2, seg = t & 3;
            cp_async16(sA + row * PSTR + seg * 16,
                       &Ap[(size_t)(row0 + row) * KD + k0 + seg * 8]);
            cp_async16(sB + row * PSTR + seg * 16,
                       &Bp[(size_t)(col0 + row) * KD + k0 + seg * 8]);
        }
    };

    auto compute = [&](int buf) {
        const uint32_t bA = smbase + buf * 2 * 128 * PSTR;
        const uint32_t bB = bA + 128 * PSTR;
        #pragma unroll
        for (int k16 = 0; k16 < 2; k16++) {
            const int kb = k16 * 32;
            uint32_t a[4][4], b[4][2];
            #pragma unroll
            for (int mt = 0; mt < 4; mt++)
                ldsm4(a[mt], a_addr(bA, PSTR, wm * 64 + mt * 16, kb, lane));
            #pragma unroll
            for (int np = 0; np < 2; np++) {
                uint32_t r[4];
                ldsm4(r, b_addr(bB, PSTR, wn * 32 + np * 16, kb, lane));
                b[np * 2 + 0][0] = r[0]; b[np * 2 + 0][1] = r[1];
                b[np * 2 + 1][0] = r[2]; b[np * 2 + 1][1] = r[3];
            }
            #pragma unroll
            for (int mt = 0; mt < 4; mt++)
                #pragma unroll
                for (int nt = 0; nt < 4; nt++)
                    mma16816(acc[mt][nt], a[mt], b[nt]);
        }
    };

    load_async(0, 0);
    CP_COMMIT();
    for (int c = 0; c < 96; c++) {
        const int buf = c & 1;
        if (c + 1 < 96) {
            load_async(c + 1, buf ^ 1);
            CP_COMMIT();
            CP_WAIT(1);              // chunk c landed; c+1 in flight
        } else {
            CP_WAIT(0);
        }
        __syncthreads();
        compute(buf);
        __syncthreads();             // before next iter's cp.async overwrites buf
    }

    #pragma unroll
    for (int mt = 0; mt < 4; mt++) {
        const int r0 = row0 + wm * 64 + mt * 16 + (lane >> 2);
        #pragma unroll
        for (int nt = 0; nt < 4; nt++) {
            const int cc = col0 + wn * 32 + nt * 8 + (lane & 3) * 2;
            #pragma unroll
            for (int half = 0; half < 2; half++) {    // row r0, r0+8
                const int row = r0 + half * 8;
                float v0 = acc[mt][nt][half * 2 + 0];
                float v1 = acc[mt][nt][half * 2 + 1];
                if (bias) { v0 += bias[cc]; v1 += bias[cc + 1]; }
                if (C) {
                    float2 o = {v0, v1};
                    *(float2*)&C[(size_t)row * ldc + cc] = o;
                }
                if (Chi) {
                    float h0, l0, h1, l1;
                    split2(v0, h0, l0);
                    split2(v1, h1, l1);
                    *(uint32_t*)&Chi[(size_t)row * ldc + cc] = pack_bf16x2(h0, h1);
                    *(uint32_t*)&Clo[(size_t)row * ldc + cc] = pack_bf16x2(l0, l1);
                }
            }
        }
    }
}

// ---------------------------------------------------------------------------
// Scores: Sc[bh][i][j] = q[bh,i,:] . (k[b,j,:] + rel[i,j,:])
// CTA = (j-tile 128, i). KR folded fp32 then hi/lo split in smem.
// Warp (b = wid>>1, jt = wid&1): M=16j N=16h K=64 x 3 products per j32-chunk.
// ---------------------------------------------------------------------------
#define SCQ 0
#define SCKR 18432
#define SCST 55296
#define SC_SMEM_TOTAL 64000
#define QSTR 144

__global__ void __launch_bounds__(256)
scores_mma(const float* __restrict__ rel, const float* __restrict__ KV,
           const __nv_bfloat16* __restrict__ qhi, const __nv_bfloat16* __restrict__ qlo,
           float* __restrict__ Sc) {
    extern __shared__ char smem[];
    const uint32_t smbase = smem_u32(smem);
    const int tid = threadIdx.x;
    const int wid = tid >> 5;
    const int lane = tid & 31;
    const int i  = blockIdx.y;
    const int j0 = blockIdx.x * 128;
    const int wb = wid >> 1;       // batch
    const int m0 = (wid & 1) * 16; // j-tile within 32-chunk

    // Q tiles: [b][half][h][64 bf16] rows padded to 144B
    #pragma unroll
    for (int t = tid; t < 1024; t += 256) {
        const int b = t >> 8, half = (t >> 7) & 1, h = (t >> 3) & 15, seg = t & 7;
        const __nv_bfloat16* src = half ? qlo : qhi;
        *(uint4*)(smem + SCQ + (b * 2 + half) * 2304 + h * QSTR + seg * 16) =
            *(const uint4*)&src[((size_t)(b * S_LEN + i)) * DM + h * DH + seg * 8];
    }

    for (int jc = 0; jc < 4; jc++) {
        const int j0c = j0 + jc * 32;
        __syncthreads();   // stage reads done (and Qs visible after 1st)

        // KR build: fold fp32 + split, rows [j][64 bf16] padded 144B
        #pragma unroll
        for (int t = tid; t < 2048; t += 256) {
            const int b = t >> 9, j = (t >> 4) & 31, d4 = t & 15;
            const float4 r4 = *(const float4*)
                &rel[((size_t)i * S_LEN + j0c + j) * DH + d4 * 4];
            const float4 k4 = *(const float4*)
                &KV[((size_t)(b * S_LEN + j0c + j)) * 128 + d4 * 4];
            float v[4] = {r4.x + k4.x, r4.y + k4.y, r4.z + k4.z, r4.w + k4.w};
            float hf[4], lf[4];
            #pragma unroll
            for (int u = 0; u < 4; u++) split2(v[u], hf[u], lf[u]);
            uint2 hv = {pack_bf16x2(hf[0], hf[1]), pack_bf16x2(hf[2], hf[3])};
            uint2 lv = {pack_bf16x2(lf[0], lf[1]), pack_bf16x2(lf[2], lf[3])};
            *(uint2*)(smem + SCKR + (b * 2 + 0) * 4608 + j * QSTR + d4 * 8) = hv;
            *(uint2*)(smem + SCKR + (b * 2 + 1) * 4608 + j * QSTR + d4 * 8) = lv;
        }
        __syncthreads();

        float c[2][4] = {};
        #pragma unroll
        for (int p = 0; p < 3; p++) {
            const uint32_t bA = smbase + SCKR + (wb * 2 + (p == 2 ? 1 : 0)) * 4608;
            const uint32_t bB = smbase + SCQ  + (wb * 2 + (p == 1 ? 1 : 0)) * 2304;
            #pragma unroll
            for (int k16 = 0; k16 < 4; k16++) {
                const int kb = k16 * 32;
                uint32_t a[4], r[4];
                ldsm4(a, a_addr(bA, QSTR, m0, kb, lane));
                ldsm4(r, b_addr(bB, QSTR, 0, kb, lane));
                uint32_t b0[2] = {r[0], r[1]}, b1[2] = {r[2], r[3]};
                mma16816(c[0], a, b0);
                mma16816(c[1], a, b1);
            }
        }

        // stage [j 32][bh 64] (272B rows)
        #pragma unroll
        for (int nt = 0; nt < 2; nt++) {
            const int jr  = m0 + (lane >> 2);
            const int col = wb * 16 + nt * 8 + (lane & 3) * 2;
            *(float2*)(smem + SCST + jr * 272 + col * 4)       = {c[nt][0], c[nt][1]};
            *(float2*)(smem + SCST + (jr + 8) * 272 + col * 4) = {c[nt][2], c[nt][3]};
        }
        __syncthreads();

        // coalesced store: thread -> (bh = tid>>2, 8 j)
        {
            const int bh = tid >> 2, jseg = tid & 3;
            float v[8];
            #pragma unroll
            for (int u = 0; u < 8; u++)
                v[u] = *(const float*)(smem + SCST + (jseg * 8 + u) * 272 + bh * 4);
            float4* dst = (float4*)&Sc[((size_t)bh * S_LEN + i) * S_LEN + j0c + jseg * 8];
            dst[0] = make_float4(v[0], v[1], v[2], v[3]);
            dst[1] = make_float4(v[4], v[5], v[6], v[7]);
        }
    }
}

// ---------------------------------------------------------------------------
__global__ void softmax_kernel(float* __restrict__ Sc) {
    const size_t base = (size_t)blockIdx.x * S_LEN;
    const int tid = threadIdx.x;
    const float scale = 0.125f;

    float v[4];
    float m = -1e30f;
    #pragma unroll
    for (int k = 0; k < 4; k++) {
        v[k] = Sc[base + tid + k * 256];
        m = fmaxf(m, v[k]);
    }
    #pragma unroll
    for (int o = 16; o; o >>= 1) m = fmaxf(m, __shfl_xor_sync(0xffffffffu, m, o));
    __shared__ float red[8];
    if ((tid & 31) == 0) red[tid >> 5] = m;
    __syncthreads();
    m = red[0];
    #pragma unroll
    for (int w = 1; w < 8; w++) m = fmaxf(m, red[w]);
    __syncthreads();

    float s = 0.f;
    #pragma unroll
    for (int k = 0; k < 4; k++) {
        v[k] = expf((v[k] - m) * scale);
        s += v[k];
    }
    #pragma unroll
    for (int o = 16; o; o >>= 1) s += __shfl_xor_sync(0xffffffffu, s, o);
    __shared__ float red2[8];
    if ((tid & 31) == 0) red2[tid >> 5] = s;
    __syncthreads();
    s = red2[0];
    #pragma unroll
    for (int w = 1; w < 8; w++) s += red2[w];
    const float inv = 1.0f / s;

    #pragma unroll
    for (int k = 0; k < 4; k++) Sc[base + tid + k * 256] = v[k] * inv;
}

// ---------------------------------------------------------------------------
// attn @ V: CTA = (bh, i-tile 128). j-chunks of 32, double-buffered.
// attn fp32 tile split hi/lo ONCE per chunk (all 3 products reuse it).
// Warp (wm = wid>>2, wn = wid&3): tile 64i x 16d.
// Fused epilogue: write ctx directly as bf16 hi/lo (chi/clo).
// ---------------------------------------------------------------------------
#define AVB 30720
#define AV_SMEM_TOTAL (2 * AVB)

__global__ void __launch_bounds__(256)
attn_v_mma(const float* __restrict__ attn,
           const __nv_bfloat16* __restrict__ vthi,
           const __nv_bfloat16* __restrict__ vtlo,
           __nv_bfloat16* __restrict__ chi, __nv_bfloat16* __restrict__ clo) {
    extern __shared__ char smem[];
    const uint32_t smbase = smem_u32(smem);
    const int tid = threadIdx.x;
    const int wid = tid >> 5;
    const int lane = tid & 31;
    const int bh = blockIdx.y, b = bh >> 4, h = bh & 15;
    const int i0 = blockIdx.x * 128;
    const int wm = wid >> 2, wn = wid & 3;
    const float* A = attn + (size_t)bh * S_LEN * S_LEN;

    float acc[4][2][4] = {};       // [mt][nt][4]

    auto load_chunk = [&](int c, int buf) {
        const int j0c = c * 32;
        char* sAh = smem + buf * AVB;
        char* sAl = sAh + 128 * PSTR;
        char* sVh = sAl + 128 * PSTR;
        char* sVl = sVh + 64 * PSTR;
        #pragma unroll
        for (int t = tid; t < 1024; t += 256) {
            const int ii = t >> 3, j4 = t & 7;
            const float4 a4 = *(const float4*)&A[(size_t)(i0 + ii) * S_LEN + j0c + j4 * 4];
            float v[4] = {a4.x, a4.y, a4.z, a4.w};
            float hf[4], lf[4];
            #pragma unroll
            for (int u = 0; u < 4; u++) split2(v[u], hf[u], lf[u]);
            *(uint2*)(sAh + ii * PSTR + j4 * 8) =
                {pack_bf16x2(hf[0], hf[1]), pack_bf16x2(hf[2], hf[3])};
            *(uint2*)(sAl + ii * PSTR + j4 * 8) =
                {pack_bf16x2(lf[0], lf[1]), pack_bf16x2(lf[2], lf[3])};
        }
        {
            const int d = tid >> 2, seg = tid & 3;    // 256 threads exactly
            *(uint4*)(sVh + d * PSTR + seg * 16) =
                *(const uint4*)&vthi[((size_t)(b * DH + d)) * S_LEN + j0c + seg * 8];
            *(uint4*)(sVl + d * PSTR + seg * 16) =
                *(const uint4*)&vtlo[((size_t)(b * DH + d)) * S_LEN + j0c + seg * 8];
        }
    };

    auto compute = [&](int buf) {
        const uint32_t bAh = smbase + buf * AVB;
        const uint32_t bAl = bAh + 128 * PSTR;
        const uint32_t bVh = bAl + 128 * PSTR;
        const uint32_t bVl = bVh + 64 * PSTR;
        #pragma unroll
        for (int p = 0; p < 3; p++) {
            const uint32_t bA = (p == 2) ? bAl : bAh;
            const uint32_t bV = (p == 1) ? bVl : bVh;
            #pragma unroll
            for (int k16 = 0; k16 < 2; k16++) {
                const int kb = k16 * 32;
                uint32_t a[4][4], r[4];
                #pragma unroll
                for (int mt = 0; mt < 4; mt++)
                    ldsm4(a[mt], a_addr(bA, PSTR, wm * 64 + mt * 16, kb, lane));
                ldsm4(r, b_addr(bV, PSTR, wn * 16, kb, lane));
                uint32_t b0[2] = {r[0], r[1]}, b1[2] = {r[2], r[3]};
                #pragma unroll
                for (int mt = 0; mt < 4; mt++) {
                    mma16816(acc[mt][0], a[mt], b0);
                    mma16816(acc[mt][1], a[mt], b1);
                }
            }
        }
    };

    load_chunk(0, 0);
    __syncthreads();
    for (int c = 0; c < 32; c++) {
        const int buf = c & 1;
        if (c + 1 < 32) load_chunk(c + 1, buf ^ 1);
        compute(buf);
        __syncthreads();
    }

    #pragma unroll
    for (int mt = 0; mt < 4; mt++) {
        const int ig = i0 + wm * 64 + mt * 16 + (lane >> 2);
        #pragma unroll
        for (int nt = 0; nt < 2; nt++) {
            const int col = h * DH + wn * 16 + nt * 8 + (lane & 3) * 2;
            #pragma unroll
            for (int half = 0; half < 2; half++) {
                const size_t row = (size_t)(b * S_LEN + ig + half * 8);
                float v0 = acc[mt][nt][half * 2 + 0];
                float v1 = acc[mt][nt][half * 2 + 1];
                float h0, l0, h1, l1;
                split2(v0, h0, l0);
                split2(v1, h1, l1);
                *(uint32_t*)&chi[row * DM + col] = pack_bf16x2(h0, h1);
                *(uint32_t*)&clo[row * DM + col] = pack_bf16x2(l0, l1);
            }
        }
    }
}

// ---------------------------------------------------------------------------
extern "C" void kernel_launch(void* const* d_in, const int* in_sizes, int n_in,
                              void* d_out, int out_size) {
    const float* x   = (const float*)d_in[0];
    const float* rel = (const float*)d_in[1];
    const float* Wq  = (const float*)d_in[2];
    const float* Wk  = (const float*)d_in[3];
    const float* Wv  = (const float*)d_in[4];
    const float* Wo  = (const float*)d_in[5];
    const float* bo  = (const float*)d_in[6];
    float* out = (float*)d_out;

    float *KV, *Sc;
    cudaGetSymbolAddress((void**)&KV, g_KV);
    cudaGetSymbolAddress((void**)&Sc, g_Sc);
    __nv_bfloat16 *xhi, *xlo, *chi, *clo, *qhi, *qlo;
    __nv_bfloat16 *wqhi, *wqlo, *wohi, *wolo, *wkvhi, *wkvlo, *vthi, *vtlo;
    cudaGetSymbolAddress((void**)&xhi, g_xhi);
    cudaGetSymbolAddress((void**)&xlo, g_xlo);
    cudaGetSymbolAddress((void**)&chi, g_chi);
    cudaGetSymbolAddress((void**)&clo, g_clo);
    cudaGetSymbolAddress((void**)&qhi, g_qhi);
    cudaGetSymbolAddress((void**)&qlo, g_qlo);
    cudaGetSymbolAddress((void**)&wqhi, g_wqhi);
    cudaGetSymbolAddress((void**)&wqlo, g_wqlo);
    cudaGetSymbolAddress((void**)&wohi, g_wohi);
    cudaGetSymbolAddress((void**)&wolo, g_wolo);
    cudaGetSymbolAddress((void**)&wkvhi, g_wkvhi);
    cudaGetSymbolAddress((void**)&wkvlo, g_wkvlo);
    cudaGetSymbolAddress((void**)&vthi, g_vthi);
    cudaGetSymbolAddress((void**)&vtlo, g_vtlo);

    cudaFuncSetAttribute(scores_mma, cudaFuncAttributeMaxDynamicSharedMemorySize,
                         SC_SMEM_TOTAL);
    cudaFuncSetAttribute(attn_v_mma, cudaFuncAttributeMaxDynamicSharedMemorySize,
                         AV_SMEM_TOTAL);

    // 0) fp32 -> bf16 hi/lo splits (inputs only)
    split_bf16<<<(ROWS * DM) / 256, 256>>>(x,  xhi, xlo, ROWS * DM);
    split_bf16<<<(DM * DM) / 256, 256>>>(Wq, wqhi, wqlo, DM * DM);
    split_bf16<<<(DM * DM) / 256, 256>>>(Wo, wohi, wolo, DM * DM);
    split_bf16<<<(DH * DM) / 256, 256>>>(Wk, wkvhi, wkvlo, DH * DM);
    split_bf16<<<(DH * DM) / 256, 256>>>(Wv, wkvhi + DH * DM, wkvlo + DH * DM, DH * DM);

    // 1) Q projection [4096x1024] -> fused hi/lo split (no fp32 Q)
    mma_gemm<<<dim3(DM / 128, ROWS / 128), 256>>>(
        xhi, xlo, wqhi, wqlo, nullptr, nullptr, qhi, qlo, DM);

    // 1b) K/V projection (stacked) [4096x128] fp32, then V^T split
    mma_gemm<<<dim3(1, ROWS / 128), 256>>>(
        xhi, xlo, wkvhi, wkvlo, nullptr, KV, nullptr, nullptr, 128);
    vt_split<<<16, 256>>>(KV, vthi, vtlo);

    // 2) Scores (folded q.(k+rel))
    scores_mma<<<dim3(S_LEN / 128, S_LEN), 256, SC_SMEM_TOTAL>>>(rel, KV, qhi, qlo, Sc);

    // 3) softmax
    softmax_kernel<<<BH * S_LEN, 256>>>(Sc);

    // 4) attn @ V -> fused hi/lo split (no fp32 ctx)
    attn_v_mma<<<dim3(S_LEN / 128, BH), 256, AV_SMEM_TOTAL>>>(Sc, vthi, vtlo, chi, clo);

    // 5) Output projection (+bias, fp32 out)
    mma_gemm<<<dim3(DM / 128, ROWS / 128), 256>>>(
        chi, clo, wohi, wolo, bo, out, nullptr, nullptr, DM);
}